// round 16
// baseline (speedup 1.0000x reference)
#include <cuda_runtime.h>
#include <cuda_bf16.h>

// NeuralODE R16: R15 with the loop-bound bug fixed (g < 8, all 64 hidden
// units). Scalar A/B of R14's algorithm: 8-way shared reciprocal (1 MUFU rcp
// per 8 sigmoids), exact u = t*2^-15 + 2^-15 prescale with clamp p<=30,
// V folded by -2^-14, o = c + sum r~*v~. Pure scalar float: no u64 packing,
// no pk/upk marshalling -- ptxas owns scheduling and pipe balance.

#define NB    131072
#define NSEQ  150
#define ND    2
#define NH    64
#define NPRED 150
#define NSTEPS (NPRED - 1)

__device__ __forceinline__ float ex2f(float p) {
    float t; asm("ex2.approx.f32 %0, %1;" : "=f"(t) : "f"(p)); return t;
}
__device__ __forceinline__ float rcpf(float p) {
    float t; asm("rcp.approx.f32 %0, %1;" : "=f"(t) : "f"(p)); return t;
}

// Shared layout (per hidden pair index jp, unit j = 2jp):
//   sW[jp] = {s*wx_j, s*wx_j1, s*wy_j, s*wy_j1}
//   sV[jp] = {v~x_j, v~x_j1, v~y_j, v~y_j1},  v~ = -2^-14 * W2
//   sB[g]  = 4 biases (s*b) for units 4g..4g+3
//   s = 2*log2(e). o = c + sum_j (2^15/u_j)*v~_j, u = 2^p+1 scaled, p <= 30.
__device__ __forceinline__ void feval(float y0, float y1,
                                      const float4* __restrict__ sW,
                                      const float4* __restrict__ sB,
                                      const float4* __restrict__ sV,
                                      float c0, float c1,
                                      float& o0, float& o1) {
    const float c15 = 0.000030517578125f;   // 2^-15 (exact)
    float a0a = 0.0f, a1a = 0.0f;
    float a0b = 0.0f, a1b = 0.0f;
#pragma unroll 4
    for (int g = 0; g < 8; g++) {            // 8 hidden units per iteration, 64 total
        float4 Wa = sW[4 * g];
        float4 Wb = sW[4 * g + 1];
        float4 Wc = sW[4 * g + 2];
        float4 Wd = sW[4 * g + 3];
        float4 B0 = sB[2 * g];
        float4 B1 = sB[2 * g + 1];

        float p0 = fmaf(y0, Wa.x, fmaf(y1, Wa.z, B0.x));
        float p1 = fmaf(y0, Wa.y, fmaf(y1, Wa.w, B0.y));
        float p2 = fmaf(y0, Wb.x, fmaf(y1, Wb.z, B0.z));
        float p3 = fmaf(y0, Wb.y, fmaf(y1, Wb.w, B0.w));
        float p4 = fmaf(y0, Wc.x, fmaf(y1, Wc.z, B1.x));
        float p5 = fmaf(y0, Wc.y, fmaf(y1, Wc.w, B1.y));
        float p6 = fmaf(y0, Wd.x, fmaf(y1, Wd.z, B1.z));
        float p7 = fmaf(y0, Wd.y, fmaf(y1, Wd.w, B1.w));

        float t0 = ex2f(fminf(p0, 30.0f));
        float t1 = ex2f(fminf(p1, 30.0f));
        float t2 = ex2f(fminf(p2, 30.0f));
        float t3 = ex2f(fminf(p3, 30.0f));
        float t4 = ex2f(fminf(p4, 30.0f));
        float t5 = ex2f(fminf(p5, 30.0f));
        float t6 = ex2f(fminf(p6, 30.0f));
        float t7 = ex2f(fminf(p7, 30.0f));

        // u' = t*2^-15 + 2^-15 (exact scaling): u' in [2^-15, 2^15+]
        float u0 = fmaf(t0, c15, c15);
        float u1 = fmaf(t1, c15, c15);
        float u2 = fmaf(t2, c15, c15);
        float u3 = fmaf(t3, c15, c15);
        float u4 = fmaf(t4, c15, c15);
        float u5 = fmaf(t5, c15, c15);
        float u6 = fmaf(t6, c15, c15);
        float u7 = fmaf(t7, c15, c15);

        // 8-way shared reciprocal: one MUFU rcp per 8 sigmoids.
        // 8-product in [2^-120, 2^120]: always normal fp32.
        float m01 = u0 * u1;
        float m23 = u2 * u3;
        float m45 = u4 * u5;
        float m67 = u6 * u7;
        float A4  = m01 * m23;
        float B4  = m45 * m67;
        float rc  = rcpf(A4 * B4);
        float iA  = rc * B4;                  // 1/A4
        float iB  = rc * A4;                  // 1/B4
        float rA  = iA * m23;                 // 1/m01
        float rB  = iA * m01;                 // 1/m23
        float rC  = iB * m67;                 // 1/m45
        float rD  = iB * m45;                 // 1/m67
        float r0  = rA * u1;                  // 1/u0
        float r1  = rA * u0;
        float r2  = rB * u3;
        float r3  = rB * u2;
        float r4  = rC * u5;
        float r5  = rC * u4;
        float r6  = rD * u7;
        float r7  = rD * u6;

        float4 Va = sV[4 * g];
        float4 Vb = sV[4 * g + 1];
        float4 Vc = sV[4 * g + 2];
        float4 Vd = sV[4 * g + 3];
        a0a = fmaf(r0, Va.x, a0a);  a1a = fmaf(r0, Va.z, a1a);
        a0b = fmaf(r1, Va.y, a0b);  a1b = fmaf(r1, Va.w, a1b);
        a0a = fmaf(r2, Vb.x, a0a);  a1a = fmaf(r2, Vb.z, a1a);
        a0b = fmaf(r3, Vb.y, a0b);  a1b = fmaf(r3, Vb.w, a1b);
        a0a = fmaf(r4, Vc.x, a0a);  a1a = fmaf(r4, Vc.z, a1a);
        a0b = fmaf(r5, Vc.y, a0b);  a1b = fmaf(r5, Vc.w, a1b);
        a0a = fmaf(r6, Vd.x, a0a);  a1a = fmaf(r6, Vd.z, a1a);
        a0b = fmaf(r7, Vd.y, a0b);  a1b = fmaf(r7, Vd.w, a1b);
    }
    o0 = c0 + (a0a + a0b);
    o1 = c1 + (a1a + a1b);
}

__global__ void __launch_bounds__(128, 7)
neural_ode_kernel(const float* __restrict__ x,
                  const float* __restrict__ W1,
                  const float* __restrict__ b1,
                  const float* __restrict__ W2,
                  const float* __restrict__ b2,
                  float* __restrict__ out) {
    __shared__ alignas(16) float4 sWf[NH / 2];
    __shared__ alignas(16) float4 sVf[NH / 2];
    __shared__ alignas(16) float4 sBf[NH / 4];
    __shared__ float sc[2];

    const int tid = threadIdx.x;
    if (tid < NH / 2) {
        const float s  = 2.8853900817779268f;   // 2*log2(e)
        const float vs = -0.00006103515625f;    // -2^-14 (exact)
        int j = 2 * tid;
        sWf[tid] = make_float4(s * W1[j], s * W1[j + 1],
                               s * W1[NH + j], s * W1[NH + j + 1]);
        sVf[tid] = make_float4(vs * W2[2 * j], vs * W2[2 * (j + 1)],
                               vs * W2[2 * j + 1], vs * W2[2 * (j + 1) + 1]);
    }
    if (tid < NH / 4) {
        const float s = 2.8853900817779268f;
        int j = 4 * tid;
        sBf[tid] = make_float4(s * b1[j], s * b1[j + 1],
                               s * b1[j + 2], s * b1[j + 3]);
    }
    if (tid < 2) {
        float c = b2[tid];
        for (int j = 0; j < NH; j++) c += W2[2 * j + tid];
        sc[tid] = c;
    }
    __syncthreads();

    const float c0 = sc[0];
    const float c1 = sc[1];

    const long b = (long)blockIdx.x * blockDim.x + tid;

    const float2 yin = *(const float2*)(x + b * (long)(NSEQ * ND) + (NSEQ - 1) * ND);
    float y0 = yin.x;
    float y1 = yin.y;

    float2* ob = (float2*)(out + b * (long)(NPRED * ND));
    ob[0] = make_float2(y0, y1);

    const float dt   = (float)(150.0 / 149.0);
    const float dt3  = dt * (1.0f / 3.0f);
    const float dt8  = dt * 0.125f;
    const float thrd = 1.0f / 3.0f;

#pragma unroll 1
    for (int st = 0; st < NSTEPS; st++) {
        float k1x, k1y, k2x, k2y, k3x, k3y, k4x, k4y;

        feval(y0, y1, sWf, sBf, sVf, c0, c1, k1x, k1y);
        feval(fmaf(dt3, k1x, y0), fmaf(dt3, k1y, y1),
              sWf, sBf, sVf, c0, c1, k2x, k2y);
        feval(fmaf(dt, fmaf(-thrd, k1x, k2x), y0),
              fmaf(dt, fmaf(-thrd, k1y, k2y), y1),
              sWf, sBf, sVf, c0, c1, k3x, k3y);
        feval(fmaf(dt, (k1x - k2x) + k3x, y0),
              fmaf(dt, (k1y - k2y) + k3y, y1),
              sWf, sBf, sVf, c0, c1, k4x, k4y);

        y0 = fmaf(dt8, fmaf(3.0f, k2x + k3x, k1x + k4x), y0);
        y1 = fmaf(dt8, fmaf(3.0f, k2y + k3y, k1y + k4y), y1);

        ob[st + 1] = make_float2(y0, y1);
    }
}

extern "C" void kernel_launch(void* const* d_in, const int* in_sizes, int n_in,
                              void* d_out, int out_size) {
    const float* x  = (const float*)d_in[0];
    const float* W1 = (const float*)d_in[1];
    const float* b1 = (const float*)d_in[2];
    const float* W2 = (const float*)d_in[3];
    const float* b2 = (const float*)d_in[4];
    float* out = (float*)d_out;

    const int block = 128;
    const int grid  = NB / block;  // 1024 CTAs, 4096 warps
    neural_ode_kernel<<<grid, block>>>(x, W1, b1, W2, b2, out);
}